// round 3
// baseline (speedup 1.0000x reference)
#include <cuda_runtime.h>
#include <mma.h>
#include <cstdint>

using namespace nvcuda;

#define BM 128
#define BN 128
#define BK 32
#define APAD 4
#define NWARPS 8

// ---- scratch (__device__ globals; no allocations allowed) ----
__device__ float g_P[8u * 256u * 4096u];   // phi  conv out, viewed [512,2048]/batch
__device__ float g_T[8u * 256u * 4096u];   // theta conv out
__device__ float g_G[8u * 256u * 4096u];   // g    conv out
__device__ float g_S[8u * 2048u * 2048u];  // S^T then normalized attn E
__device__ float g_O[8u * 256u * 4096u];   // out_nl, viewed [256,4096]/batch

// ============================================================================
// Tiled TF32 wmma GEMM: C[b] = A[b] @ B[b] (+ bias[row]) (+ addend[b])
//   A: TRANS_A ? [K,M] row-major (lda=M)  :  [M,K] row-major (lda=K)
//   B: [K,N] row-major
//   EPI: 0 = plain store, 1 = +bias[gm], 2 = +bias[gm] + addend[b][gm][gn]
// M % 128 == 0, N % 128 == 0, K % 32 == 0 (true for all calls here)
// ============================================================================
template <bool TRANS_A, int EPI>
__global__ __launch_bounds__(256, 2)
void gemm_tf32_kernel(const float* __restrict__ A, const float* __restrict__ B,
                      float* __restrict__ C, const float* __restrict__ bias,
                      const float* __restrict__ addend,
                      int M, int N, int K,
                      long long sA, long long sB, long long sC, long long sAdd)
{
    __shared__ __align__(16) float As[BK][BM + APAD];  // As[k][m] (col-major A tile)
    __shared__ __align__(16) float Bs[BK][BN + APAD];  // Bs[k][n]
    __shared__ __align__(16) float epi[NWARPS][256];

    const int bn0 = blockIdx.x * BN;
    const int bm0 = blockIdx.y * BM;
    const int batch = blockIdx.z;

    const float* Ab = A + (long long)batch * sA;
    const float* Bb = B + (long long)batch * sB;
    float* Cb = C + (long long)batch * sC;

    const int tid = threadIdx.x;
    const int warpId = tid >> 5;
    const int lane = tid & 31;
    const int wm = warpId >> 2;  // 0..1  (64-row warp tile)
    const int wn = warpId & 3;   // 0..3  (32-col warp tile)

    wmma::fragment<wmma::accumulator, 16, 16, 8, float> acc[4][2];
#pragma unroll
    for (int i = 0; i < 4; i++)
#pragma unroll
        for (int j = 0; j < 2; j++) wmma::fill_fragment(acc[i][j], 0.0f);

    for (int k0 = 0; k0 < K; k0 += BK) {
        // ---- stage A tile into As[k][m] (tf32-rounded) ----
        if (TRANS_A) {
            const int lda = M;
#pragma unroll
            for (int it = 0; it < 4; it++) {
                int slot = tid + it * 256;      // 0..1023 float4 slots of 32x128
                int k  = slot >> 5;             // 0..31
                int c4 = slot & 31;             // 0..31
                float4 v = *reinterpret_cast<const float4*>(
                    Ab + (long long)(k0 + k) * lda + bm0 + c4 * 4);
                v.x = wmma::__float_to_tf32(v.x);
                v.y = wmma::__float_to_tf32(v.y);
                v.z = wmma::__float_to_tf32(v.z);
                v.w = wmma::__float_to_tf32(v.w);
                *reinterpret_cast<float4*>(&As[k][c4 * 4]) = v;
            }
        } else {
            const int lda = K;
#pragma unroll
            for (int it = 0; it < 4; it++) {
                int slot = tid + it * 256;      // 0..1023 float4 slots of 128x8
                int m  = slot >> 3;             // 0..127
                int c4 = slot & 7;              // 0..7
                float4 v = *reinterpret_cast<const float4*>(
                    Ab + (long long)(bm0 + m) * lda + k0 + c4 * 4);
                As[c4 * 4 + 0][m] = wmma::__float_to_tf32(v.x);
                As[c4 * 4 + 1][m] = wmma::__float_to_tf32(v.y);
                As[c4 * 4 + 2][m] = wmma::__float_to_tf32(v.z);
                As[c4 * 4 + 3][m] = wmma::__float_to_tf32(v.w);
            }
        }
        // ---- stage B tile into Bs[k][n] ----
#pragma unroll
        for (int it = 0; it < 4; it++) {
            int slot = tid + it * 256;
            int k  = slot >> 5;
            int c4 = slot & 31;
            float4 v = *reinterpret_cast<const float4*>(
                Bb + (long long)(k0 + k) * N + bn0 + c4 * 4);
            v.x = wmma::__float_to_tf32(v.x);
            v.y = wmma::__float_to_tf32(v.y);
            v.z = wmma::__float_to_tf32(v.z);
            v.w = wmma::__float_to_tf32(v.w);
            *reinterpret_cast<float4*>(&Bs[k][c4 * 4]) = v;
        }
        __syncthreads();

#pragma unroll
        for (int kk = 0; kk < BK; kk += 8) {
            wmma::fragment<wmma::matrix_a, 16, 16, 8, wmma::precision::tf32,
                           wmma::col_major> af[4];
            wmma::fragment<wmma::matrix_b, 16, 16, 8, wmma::precision::tf32,
                           wmma::row_major> bf[2];
#pragma unroll
            for (int i = 0; i < 4; i++)
                wmma::load_matrix_sync(af[i], &As[kk][wm * 64 + i * 16], BM + APAD);
#pragma unroll
            for (int j = 0; j < 2; j++)
                wmma::load_matrix_sync(bf[j], &Bs[kk][wn * 32 + j * 16], BN + APAD);
#pragma unroll
            for (int i = 0; i < 4; i++)
#pragma unroll
                for (int j = 0; j < 2; j++)
                    wmma::mma_sync(acc[i][j], af[i], bf[j], acc[i][j]);
        }
        __syncthreads();
    }

    // ---- epilogue ----
    if (EPI == 0) {
#pragma unroll
        for (int i = 0; i < 4; i++)
#pragma unroll
            for (int j = 0; j < 2; j++) {
                int gm = bm0 + wm * 64 + i * 16;
                int gn = bn0 + wn * 32 + j * 16;
                wmma::store_matrix_sync(Cb + (long long)gm * N + gn, acc[i][j], N,
                                        wmma::mem_row_major);
            }
    } else {
#pragma unroll
        for (int i = 0; i < 4; i++)
#pragma unroll
            for (int j = 0; j < 2; j++) {
                wmma::store_matrix_sync(&epi[warpId][0], acc[i][j], 16,
                                        wmma::mem_row_major);
                __syncwarp();
#pragma unroll
                for (int e = 0; e < 8; e++) {
                    int idx = lane * 8 + e;  // 0..255 within the 16x16 tile
                    int r = idx >> 4, cl = idx & 15;
                    int gm = bm0 + wm * 64 + i * 16 + r;
                    int gn = bn0 + wn * 32 + j * 16 + cl;
                    float v = epi[warpId][idx] + bias[gm];
                    if (EPI == 2)
                        v += addend[(long long)batch * sAdd + (long long)gm * N + gn];
                    Cb[(long long)gm * N + gn] = v;
                }
                __syncwarp();
            }
    }
}

// ============================================================================
// Row softmax over S^T rows (length 2048). One block of 256 threads per row.
// Writes exp(v - max)/sum in place (i.e., fully normalized attn).
// ============================================================================
__global__ void softmax_rows_kernel(float* __restrict__ S)
{
    float* row = S + (size_t)blockIdx.x * 2048u;
    const int tid = threadIdx.x, lane = tid & 31, warp = tid >> 5;

    float4 a = reinterpret_cast<float4*>(row)[tid];
    float4 b = reinterpret_cast<float4*>(row)[tid + 256];

    float m = fmaxf(fmaxf(fmaxf(a.x, a.y), fmaxf(a.z, a.w)),
                    fmaxf(fmaxf(b.x, b.y), fmaxf(b.z, b.w)));
#pragma unroll
    for (int o = 16; o > 0; o >>= 1) m = fmaxf(m, __shfl_xor_sync(0xffffffffu, m, o));

    __shared__ float red[8];
    if (lane == 0) red[warp] = m;
    __syncthreads();
    float rm = red[0];
#pragma unroll
    for (int i = 1; i < 8; i++) rm = fmaxf(rm, red[i]);
    __syncthreads();

    a.x = __expf(a.x - rm); a.y = __expf(a.y - rm);
    a.z = __expf(a.z - rm); a.w = __expf(a.w - rm);
    b.x = __expf(b.x - rm); b.y = __expf(b.y - rm);
    b.z = __expf(b.z - rm); b.w = __expf(b.w - rm);

    float s = a.x + a.y + a.z + a.w + b.x + b.y + b.z + b.w;
#pragma unroll
    for (int o = 16; o > 0; o >>= 1) s += __shfl_xor_sync(0xffffffffu, s, o);
    if (lane == 0) red[warp] = s;
    __syncthreads();
    float rs = red[0];
#pragma unroll
    for (int i = 1; i < 8; i++) rs += red[i];

    float inv = 1.0f / rs;
    a.x *= inv; a.y *= inv; a.z *= inv; a.w *= inv;
    b.x *= inv; b.y *= inv; b.z *= inv; b.w *= inv;

    reinterpret_cast<float4*>(row)[tid]       = a;
    reinterpret_cast<float4*>(row)[tid + 256] = b;
}

// ============================================================================
extern "C" void kernel_launch(void* const* d_in, const int* in_sizes, int n_in,
                              void* d_out, int out_size)
{
    const float* x       = (const float*)d_in[0];
    const float* y       = (const float*)d_in[1];
    const float* w_phi   = (const float*)d_in[2];
    const float* b_phi   = (const float*)d_in[3];
    const float* w_theta = (const float*)d_in[4];
    const float* b_theta = (const float*)d_in[5];
    const float* w_g     = (const float*)d_in[6];
    const float* b_g     = (const float*)d_in[7];
    const float* w_mask  = (const float*)d_in[8];
    const float* b_mask  = (const float*)d_in[9];
    float* out = (float*)d_out;

    float *P, *T, *G, *S, *O;
    cudaGetSymbolAddress((void**)&P, g_P);
    cudaGetSymbolAddress((void**)&T, g_T);
    cudaGetSymbolAddress((void**)&G, g_G);
    cudaGetSymbolAddress((void**)&S, g_S);
    cudaGetSymbolAddress((void**)&O, g_O);

    const dim3 blk(256);
    const long long sImg  = 512LL * 4096;   // x/y per-batch stride
    const long long sHalf = 256LL * 4096;   // conv-out per-batch stride (== 512*2048)
    const long long sS    = 2048LL * 2048;  // scores per-batch stride

    // 1) conv1x1's: [256,512] x [512,4096] (+bias per row)
    gemm_tf32_kernel<false, 1><<<dim3(32, 2, 8), blk>>>(
        w_phi, y, P, b_phi, nullptr, 256, 4096, 512, 0, sImg, sHalf, 0);
    gemm_tf32_kernel<false, 1><<<dim3(32, 2, 8), blk>>>(
        w_theta, x, T, b_theta, nullptr, 256, 4096, 512, 0, sImg, sHalf, 0);
    gemm_tf32_kernel<false, 1><<<dim3(32, 2, 8), blk>>>(
        w_g, x, G, b_g, nullptr, 256, 4096, 512, 0, sImg, sHalf, 0);

    // 2) S^T[m,n] = sum_c phi_v[c,m] * theta_v[c,n]   (A transposed: [K=512, M=2048])
    gemm_tf32_kernel<true, 0><<<dim3(16, 16, 8), blk>>>(
        P, T, S, nullptr, nullptr, 2048, 2048, 512, sHalf, sHalf, sS, 0);

    // 3) row softmax over n (== reference softmax over axis 1), normalized in place
    softmax_rows_kernel<<<8 * 2048, 256>>>(S);

    // 4) Out_v[c,n] = sum_m g_v[c,m] * E[m,n]   ([512,2048] x [2048,2048])
    gemm_tf32_kernel<false, 0><<<dim3(16, 4, 8), blk>>>(
        G, S, O, nullptr, nullptr, 512, 2048, 2048, sHalf, sS, sHalf, 0);

    // 5) out = w_mask @ Out(view [256,4096]) + b_mask + x
    gemm_tf32_kernel<false, 2><<<dim3(32, 4, 8), blk>>>(
        w_mask, O, out, b_mask, x, 512, 4096, 256, 0, sHalf, sImg, sImg);
}